// round 17
// baseline (speedup 1.0000x reference)
#include <cuda_runtime.h>
#include <cuda_fp16.h>
#include <stdint.h>

#define D_MODEL 1024
#define NHEADS  16
#define HD      64
#define BATCH   4
#define SEQ     2048
#define BH      64
#define MTOK    8192
#define QSCALE  0.18033688011112042f   // 0.125 * log2(e)
#define LOG2E   1.4426950408889634f
#define NCTA    296

// ---------------- scratch globals (allocation-free) ----------------
__device__ __half g_q[8388608];          // Q fp16 (scaled) [bh][s][d]
__device__ __half g_k[8388608];          // K fp16
__device__ __half g_v[8388608];          // V fp16
__device__ __half g_x[8388608];          // x fp16
__device__ __half g_w[4194304];          // 4 x W fp16
__device__ __half g_c[8388608];          // ctx fp16

// ---------------- helpers ----------------
__device__ __forceinline__ uint32_t su32(const void* p) {
    uint32_t a;
    asm("{ .reg .u64 t; cvta.to.shared.u64 t, %1; cvt.u32.u64 %0, t; }" : "=r"(a) : "l"(p));
    return a;
}
__device__ __forceinline__ void cpa16(uint32_t dst, const void* src) {
    asm volatile("cp.async.cg.shared.global [%0], [%1], 16;" :: "r"(dst), "l"(src));
}
__device__ __forceinline__ void cpa4(uint32_t dst, const void* src) {
    asm volatile("cp.async.ca.shared.global [%0], [%1], 4;" :: "r"(dst), "l"(src));
}
#define CP_COMMIT() asm volatile("cp.async.commit_group;" ::: "memory")
#define CP_WAIT0()  asm volatile("cp.async.wait_group 0;" ::: "memory")
#define CP_WAIT1()  asm volatile("cp.async.wait_group 1;" ::: "memory")

__device__ __forceinline__ void ldsm4(uint32_t* r, uint32_t addr) {
    asm volatile("ldmatrix.sync.aligned.m8n8.x4.shared.b16 {%0,%1,%2,%3}, [%4];"
                 : "=r"(r[0]), "=r"(r[1]), "=r"(r[2]), "=r"(r[3]) : "r"(addr));
}
__device__ __forceinline__ void ldsm4t(uint32_t* r, uint32_t addr) {
    asm volatile("ldmatrix.sync.aligned.m8n8.x4.trans.shared.b16 {%0,%1,%2,%3}, [%4];"
                 : "=r"(r[0]), "=r"(r[1]), "=r"(r[2]), "=r"(r[3]) : "r"(addr));
}
__device__ __forceinline__ void mma_f16(float* c, const uint32_t* a, const uint32_t* b) {
    asm volatile("mma.sync.aligned.m16n8k16.row.col.f32.f16.f16.f32 "
                 "{%0,%1,%2,%3}, {%4,%5,%6,%7}, {%8,%9}, {%0,%1,%2,%3};"
                 : "+f"(c[0]), "+f"(c[1]), "+f"(c[2]), "+f"(c[3])
                 : "r"(a[0]), "r"(a[1]), "r"(a[2]), "r"(a[3]), "r"(b[0]), "r"(b[1]));
}
__device__ __forceinline__ float ex2f(float x) {
    float r; asm("ex2.approx.f32 %0, %1;" : "=f"(r) : "f"(x)); return r;
}
__device__ __forceinline__ uint32_t pack2h(float v0, float v1) {
    __half2 p = __floats2half2_rn(v0, v1);
    return *(uint32_t*)&p;
}

// ---------------- prep ----------------
__global__ void split_x_kernel(const float* __restrict__ src) {
    for (size_t i = (size_t)blockIdx.x * blockDim.x + threadIdx.x; i < (size_t)MTOK * D_MODEL;
         i += (size_t)gridDim.x * blockDim.x)
        g_x[i] = __float2half_rn(src[i]);
}
__global__ void split_w_kernel(const float* __restrict__ w0, const float* __restrict__ w1,
                               const float* __restrict__ w2, const float* __restrict__ w3) {
    int idx = blockIdx.y;
    const float* src = (idx == 0) ? w0 : (idx == 1) ? w1 : (idx == 2) ? w2 : w3;
    size_t off = (size_t)idx * 1048576;
    for (size_t i = (size_t)blockIdx.x * blockDim.x + threadIdx.x; i < 1048576;
         i += (size_t)gridDim.x * blockDim.x)
        g_w[off + i] = __float2half_rn(src[i]);
}

// ---------------- projection GEMM: persistent, 128m x 128n, fp16, 64-wide k-slabs ----
// OPROJ=0: 1536 tiles = mode(3) x mx(64) x ny(8). OPROJ=1: 512 tiles.
#define PST 36864

template<int OPROJ>
__global__ void __launch_bounds__(256, 2)
proj_kernel(const float* __restrict__ bias, float* __restrict__ out)
{
    extern __shared__ char smem[];
    const uint32_t sb = su32(smem);
    const int tid = threadIdx.x;
    const int lane = tid & 31, wid = tid >> 5;
    const int wm = wid >> 2, wn = wid & 3;
    const int g = lane >> 2, tig = lane & 3;
    const int ntiles = OPROJ ? 512 : 1536;

    for (int tile = blockIdx.x; tile < ntiles; tile += gridDim.x) {
        const int mode = OPROJ ? 3 : (tile >> 9);
        const int rest = OPROJ ? tile : (tile & 511);
        const int m0 = (rest & 63) * 128;
        const int n0 = (rest >> 6) * 128;

        const __half* A = OPROJ ? g_c : g_x;
        const __half* B = g_w + (size_t)mode * 1048576;

        float acc[4][4][4];
#pragma unroll
        for (int i = 0; i < 4; i++)
#pragma unroll
            for (int j = 0; j < 4; j++)
#pragma unroll
                for (int e = 0; e < 4; e++) acc[i][j][e] = 0.0f;

        auto load_stage = [&](int kt, int buf) {
            uint32_t base = sb + buf * PST;
#pragma unroll
            for (int t = 0; t < 8; t++) {
                int vi = tid + t * 256;
                int tl = vi >> 10;
                int row = (vi >> 3) & 127;
                int ch = vi & 7;
                const __half* src = (tl ? B + (size_t)(n0 + row) * 1024
                                        : A + (size_t)(m0 + row) * 1024) + kt + ch * 8;
                cpa16(base + tl * 18432 + row * 144 + ch * 16, src);
            }
            CP_COMMIT();
        };

        load_stage(0, 0);
        for (int s = 0; s < 16; s++) {
            if (s < 15) { load_stage((s + 1) * 64, (s + 1) & 1); CP_WAIT1(); }
            else CP_WAIT0();
            __syncthreads();
            uint32_t base = sb + (s & 1) * PST;
#pragma unroll
            for (int ks = 0; ks < 4; ks++) {
                uint32_t af[4][4];
#pragma unroll
                for (int mf = 0; mf < 4; mf++) {
                    uint32_t a = base + (uint32_t)(wm * 64 + mf * 16 + (lane & 15)) * 144
                               + (ks * 16 + (lane >> 4) * 8) * 2;
                    ldsm4(af[mf], a);
                }
#pragma unroll
                for (int g2 = 0; g2 < 2; g2++) {
                    uint32_t bf[4];
                    uint32_t a = base + 18432
                               + (uint32_t)(wn * 32 + g2 * 16 + (lane & 7) + ((lane >> 4) << 3)) * 144
                               + (ks * 16 + ((lane >> 3) & 1) * 8) * 2;
                    ldsm4(bf, a);
#pragma unroll
                    for (int mf = 0; mf < 4; mf++)
#pragma unroll
                        for (int j = 0; j < 2; j++)
                            mma_f16(acc[mf][g2 * 2 + j], af[mf], &bf[j * 2]);
                }
            }
            __syncthreads();
        }

        // epilogue
        const float scale = (mode == 0) ? QSCALE : 1.0f;
#pragma unroll
        for (int mf = 0; mf < 4; mf++) {
#pragma unroll
            for (int half = 0; half < 2; half++) {
                int m = m0 + wm * 64 + mf * 16 + g + half * 8;
#pragma unroll
                for (int nf = 0; nf < 4; nf++) {
                    int n = n0 + wn * 32 + nf * 8 + 2 * tig;
                    float v0 = acc[mf][nf][half * 2] * scale;
                    float v1 = acc[mf][nf][half * 2 + 1] * scale;
                    if (OPROJ) {
                        float2 o = make_float2(v0 + bias[n], v1 + bias[n + 1]);
                        *(float2*)(out + (size_t)m * 1024 + n) = o;
                    } else {
                        int b = m >> 11, ss = m & 2047;
                        int h = n >> 6, d = n & 63;
                        size_t addr = (((size_t)(b * 16 + h) * 2048) + ss) * 64 + d;
                        __half* D = (mode == 0) ? g_q : (mode == 1) ? g_k : g_v;
                        *(uint32_t*)(D + addr) = pack2h(v0, v1);
                    }
                }
            }
        }
        __syncthreads();   // all stores done before next tile reuses smem
    }
}

// ---------------- attention: persistent, fp16, 4 warps x 32 q-rows, double-buffered ----
// 1024 tiles = qi(16) x bh(64). 128 threads, 2 CTAs/SM.
#define AT_TS  18432
#define AT_Q   0
#define AT_KV  18432
#define AT_KVS 36864
#define AT_SB  92160
#define AT_SMEM 94208

__global__ void __launch_bounds__(128, 2)
attn_kernel(const float* __restrict__ bias_table)
{
    extern __shared__ char smem[];
    const uint32_t sb = su32(smem);
    const int tid = threadIdx.x;
    const int lane = tid & 31, w = tid >> 5;    // 4 warps
    const int g = lane >> 2, tig = lane & 3;
    const int d0[2] = { w * 32 + g - 2 * tig + 127,
                        w * 32 + 16 + g - 2 * tig + 127 };

    for (int tile = blockIdx.x; tile < 1024; tile += gridDim.x) {
        const int bh = tile & 63;
        const int b = bh >> 4, h = bh & 15;
        const int q0 = (tile >> 6) * 128;

        auto issue_kv = [&](int buf, int k0) {
            uint32_t base = sb + AT_KV + buf * AT_KVS;
#pragma unroll
            for (int u = 0; u < 16; u++) {
                int vi = tid + u * 128;
                int tl = vi >> 10;          // 0 K, 1 V
                int row = (vi >> 3) & 127;
                int ch = vi & 7;
                const __half* src = (tl ? g_v : g_k)
                    + ((size_t)bh * 2048 + k0 + row) * 64 + ch * 8;
                cpa16(base + tl * AT_TS + row * 144 + ch * 16, src);
            }
            // bias window: 255 floats
            cpa4(sb + AT_SB + buf * 1024 + tid * 4,
                 bias_table + (size_t)(q0 - k0 + 1920 + tid) * 16 + h);
            if (tid < 127)
                cpa4(sb + AT_SB + buf * 1024 + (tid + 128) * 4,
                     bias_table + (size_t)(q0 - k0 + 2048 + tid) * 16 + h);
        };

        // Q tile: 1024 x 16B chunks, 128 threads -> 8 iters
#pragma unroll
        for (int t2 = 0; t2 < 8; t2++) {
            int vi = tid + t2 * 128;
            int row = (vi >> 3) & 127;
            int ch = vi & 7;
            cpa16(sb + AT_Q + row * 144 + ch * 16,
                  g_q + ((size_t)bh * 2048 + q0 + row) * 64 + ch * 8);
        }
        issue_kv(0, 0);
        CP_COMMIT();   // group: Q + KV0

        float oacc[2][8][4];
#pragma unroll
        for (int mf = 0; mf < 2; mf++)
#pragma unroll
            for (int i = 0; i < 8; i++)
#pragma unroll
                for (int e = 0; e < 4; e++) oacc[mf][i][e] = 0.0f;
        float lsA[2] = {0.0f, 0.0f}, lsB[2] = {0.0f, 0.0f};

        for (int t = 0; t < 16; t++) {
            if (t < 15) { issue_kv((t + 1) & 1, (t + 1) * 128); CP_COMMIT(); CP_WAIT1(); }
            else CP_WAIT0();
            __syncthreads();

            const uint32_t kvb = sb + AT_KV + (t & 1) * AT_KVS;
            const float* sbias = (const float*)(smem + AT_SB + (t & 1) * 1024);

#pragma unroll
            for (int half = 0; half < 2; half++) {
                // ---- S(half) = Q @ K[half]^T ----
                float sacc[2][8][4];
#pragma unroll
                for (int mf = 0; mf < 2; mf++)
#pragma unroll
                    for (int i = 0; i < 8; i++)
#pragma unroll
                        for (int e = 0; e < 4; e++) sacc[mf][i][e] = 0.0f;
#pragma unroll
                for (int ks = 0; ks < 4; ks++) {
                    uint32_t qf[2][4];
#pragma unroll
                    for (int mf = 0; mf < 2; mf++) {
                        uint32_t a = sb + AT_Q
                            + (uint32_t)(w * 32 + mf * 16 + (lane & 15)) * 144
                            + (ks * 16 + (lane >> 4) * 8) * 2;
                        ldsm4(qf[mf], a);
                    }
                    uint32_t kf[4][4];
#pragma unroll
                    for (int g2 = 0; g2 < 4; g2++) {
                        uint32_t a = kvb
                            + (uint32_t)(half * 64 + g2 * 16 + (lane & 7) + ((lane >> 4) << 3)) * 144
                            + (ks * 16 + ((lane >> 3) & 1) * 8) * 2;
                        ldsm4(kf[g2], a);
                    }
#pragma unroll
                    for (int mf = 0; mf < 2; mf++)
#pragma unroll
                        for (int nf2 = 0; nf2 < 8; nf2++)
                            mma_f16(sacc[mf][nf2], qf[mf], &kf[nf2 >> 1][(nf2 & 1) * 2]);
                }

                // ---- P(half) = 2^(S + bias*log2e) ----
                uint32_t pf[2][4][4];
#pragma unroll
                for (int mf = 0; mf < 2; mf++) {
#pragma unroll
                    for (int ks2 = 0; ks2 < 4; ks2++) {
#pragma unroll
                        for (int j = 0; j < 2; j++) {
                            int nf2 = 2 * ks2 + j;
                            float* c = sacc[mf][nf2];
                            int idx = d0[mf] - (half * 8 + nf2) * 8;
                            float p0 = ex2f(fmaf(sbias[idx],     LOG2E, c[0]));
                            float p1 = ex2f(fmaf(sbias[idx - 1], LOG2E, c[1]));
                            float p2 = ex2f(fmaf(sbias[idx + 8], LOG2E, c[2]));
                            float p3 = ex2f(fmaf(sbias[idx + 7], LOG2E, c[3]));
                            lsA[mf] += p0 + p1;
                            lsB[mf] += p2 + p3;
                            pf[mf][ks2][j * 2 + 0] = pack2h(p0, p1);
                            pf[mf][ks2][j * 2 + 1] = pack2h(p2, p3);
                        }
                    }
                }

                // ---- O += P(half) @ V[half] ----
                const uint32_t vb = kvb + AT_TS;
#pragma unroll
                for (int ks2 = 0; ks2 < 4; ks2++) {
                    uint32_t vf[4][4];
#pragma unroll
                    for (int dblk = 0; dblk < 4; dblk++) {
                        uint32_t a = vb
                            + (uint32_t)(half * 64 + ks2 * 16 + (lane & 7) + ((lane >> 3) & 1) * 8) * 144
                            + (dblk * 16 + ((lane >> 4) << 3)) * 2;
                        ldsm4t(vf[dblk], a);
                    }
#pragma unroll
                    for (int mf = 0; mf < 2; mf++)
#pragma unroll
                        for (int dblk = 0; dblk < 4; dblk++)
#pragma unroll
                            for (int sub = 0; sub < 2; sub++)
                                mma_f16(oacc[mf][dblk * 2 + sub], pf[mf][ks2], &vf[dblk][sub * 2]);
                }
            }
            __syncthreads();
        }

        // ---- row-sum reduce within quad, epilogue (per m-frag) ----
#pragma unroll
        for (int mf = 0; mf < 2; mf++) {
            lsA[mf] += __shfl_xor_sync(0xffffffffu, lsA[mf], 1);
            lsA[mf] += __shfl_xor_sync(0xffffffffu, lsA[mf], 2);
            lsB[mf] += __shfl_xor_sync(0xffffffffu, lsB[mf], 1);
            lsB[mf] += __shfl_xor_sync(0xffffffffu, lsB[mf], 2);
            const float inv0 = 1.0f / lsA[mf];
            const float inv1 = 1.0f / lsB[mf];
            const int row0 = q0 + w * 32 + mf * 16 + g;
            const size_t base0 = (size_t)(b * 2048 + row0) * 1024 + h * 64;
            const size_t base1 = (size_t)(b * 2048 + row0 + 8) * 1024 + h * 64;
#pragma unroll
            for (int nfd = 0; nfd < 8; nfd++) {
                int d = nfd * 8 + 2 * tig;
                *(uint32_t*)(g_c + base0 + d) = pack2h(oacc[mf][nfd][0] * inv0, oacc[mf][nfd][1] * inv0);
                *(uint32_t*)(g_c + base1 + d) = pack2h(oacc[mf][nfd][2] * inv1, oacc[mf][nfd][3] * inv1);
            }
        }
        __syncthreads();   // smem safe to reuse next tile
    }
}

// ---------------- launch ----------------
extern "C" void kernel_launch(void* const* d_in, const int* in_sizes, int n_in,
                              void* d_out, int out_size)
{
    const float* x  = (const float*)d_in[0];
    const float* Wq = (const float*)d_in[1];
    const float* Wk = (const float*)d_in[2];
    const float* Wv = (const float*)d_in[3];
    const float* Wo = (const float*)d_in[4];
    const float* bo = (const float*)d_in[5];
    const float* bt = (const float*)d_in[6];
    float* out = (float*)d_out;

    cudaFuncSetAttribute(proj_kernel<0>, cudaFuncAttributeMaxDynamicSharedMemorySize, 2 * PST);
    cudaFuncSetAttribute(proj_kernel<1>, cudaFuncAttributeMaxDynamicSharedMemorySize, 2 * PST);
    cudaFuncSetAttribute(attn_kernel,    cudaFuncAttributeMaxDynamicSharedMemorySize, AT_SMEM);

    split_x_kernel<<<2048, 256>>>(x);
    split_w_kernel<<<dim3(256, 4), 256>>>(Wq, Wk, Wv, Wo);

    proj_kernel<0><<<NCTA, 256, 2 * PST>>>(nullptr, nullptr);

    attn_kernel<<<NCTA, 128, AT_SMEM>>>(bt);

    proj_kernel<1><<<NCTA, 256, 2 * PST>>>(bo, out);
}